// round 14
// baseline (speedup 1.0000x reference)
#include <cuda_runtime.h>
#include <cuda_fp16.h>
#include <math.h>
#include <stdint.h>

#define Bn   16384
#define TOK  128          // tokens per CTA (8 batches; 2 per warp, 4 warps)
#define NTH  128
#define EPSV 1e-5f
#define SCL  0.25f

// Weights pre-packed in b-fragment order: per 64x64 matrix, 512 uint4:
//   index = (ks*4 + nbp)*32 + lane ; uint4 = {b0,b1 of n-block 2*nbp ; b0,b1 of 2*nbp+1}
// Matrices: 0-15 head h*{Wq,Wk,Wv,Wp}; 16-19 W1 chunks; 20-23 W2 chunks
__device__ __align__(16) uint4 gWf[24 * 512];

// ---------------- PTX helpers ----------------
__device__ __forceinline__ void mma16816(float* d, const uint32_t* a, const uint32_t* b) {
    asm volatile("mma.sync.aligned.m16n8k16.row.col.f32.f16.f16.f32 "
                 "{%0,%1,%2,%3},{%4,%5,%6,%7},{%8,%9},{%0,%1,%2,%3};"
                 : "+f"(d[0]), "+f"(d[1]), "+f"(d[2]), "+f"(d[3])
                 : "r"(a[0]), "r"(a[1]), "r"(a[2]), "r"(a[3]), "r"(b[0]), "r"(b[1]));
}
__device__ __forceinline__ uint32_t h2u(float a, float b) {
    __half2 h = __floats2half2_rn(a, b);
    return *(uint32_t*)&h;
}
__device__ __forceinline__ uint32_t movm(uint32_t s) {
    uint32_t d;
    asm volatile("movmatrix.sync.aligned.m8n8.trans.b16 %0, %1;" : "=r"(d) : "r"(s));
    return d;
}

// 16-col-block GEMM (2 batches): C_fb[16x16 per batch] = A[16x64] @ W[:, fb*16..+15]
// B fragment loaded once per (ks), used for both batches.
__device__ __forceinline__ void wgemm16c(const uint32_t a[2][4][4],
                                         const uint4* __restrict__ wf, int fb,
                                         int lane, float acc[2][2][4]) {
#pragma unroll
    for (int ks = 0; ks < 4; ++ks) {
        uint4 q = __ldg(wf + (ks * 4 + fb) * 32 + lane);
        uint32_t bA[2] = {q.x, q.y}, bB[2] = {q.z, q.w};
#pragma unroll
        for (int bi = 0; bi < 2; ++bi) {
            mma16816(acc[bi][0], a[bi][ks], bA);
            mma16816(acc[bi][1], a[bi][ks], bB);
        }
    }
}
// bias init for a 16-col block (both batches)
__device__ __forceinline__ void init8x2(float acc[2][2][4], const float* bias16, int c2) {
#pragma unroll
    for (int j = 0; j < 2; ++j) {
        float2 bv = __ldg((const float2*)(bias16 + 8 * j + c2));
#pragma unroll
        for (int bi = 0; bi < 2; ++bi) {
            acc[bi][j][0] = bv.x; acc[bi][j][1] = bv.y;
            acc[bi][j][2] = bv.x; acc[bi][j][3] = bv.y;
        }
    }
}
// full-width C-fragment (fp32, 16x64) -> A-fragment (half2)
__device__ __forceinline__ void c2a(const float cc[8][4], uint32_t a[4][4]) {
#pragma unroll
    for (int ks = 0; ks < 4; ++ks) {
#pragma unroll
        for (int t = 0; t < 2; ++t) {
            a[ks][2 * t]     = h2u(cc[2 * ks + t][0], cc[2 * ks + t][1]);
            a[ks][2 * t + 1] = h2u(cc[2 * ks + t][2], cc[2 * ks + t][3]);
        }
    }
}

// ---------------- weight pack: fp32 -> fp16 b-fragment order ----------------
__global__ void pack_weights(const float* __restrict__ Wq, const float* __restrict__ Wk,
                             const float* __restrict__ Wv, const float* __restrict__ Wp,
                             const float* __restrict__ W1, const float* __restrict__ W2) {
    int m = blockIdx.x, tid = threadIdx.x;
    const float* src;
    int stride;
    if (m < 16) {
        int h = m >> 2, t = m & 3;
        const float* w = (t == 0) ? Wq : (t == 1) ? Wk : (t == 2) ? Wv : Wp;
        src = w + h * 4096; stride = 64;
    } else if (m < 20) {
        src = W1 + (m - 16) * 64; stride = 256;   // W1[:, cc*64 .. +63]
    } else {
        src = W2 + (m - 20) * 4096; stride = 64;  // W2[cc*64 .. +63, :]
    }
    for (int idx = tid; idx < 512; idx += 256) {
        int lane = idx & 31, nbp = (idx >> 5) & 3, ks = idx >> 7;
        int c = lane & 3, r = lane >> 2;
        int kb = ks * 16 + 2 * c;
        int n0 = nbp * 16 + r, n1 = n0 + 8;
        uint4 q;
        q.x = h2u(src[kb * stride + n0],       src[(kb + 1) * stride + n0]);
        q.y = h2u(src[(kb + 8) * stride + n0], src[(kb + 9) * stride + n0]);
        q.z = h2u(src[kb * stride + n1],       src[(kb + 1) * stride + n1]);
        q.w = h2u(src[(kb + 8) * stride + n1], src[(kb + 9) * stride + n1]);
        gWf[m * 512 + idx] = q;
    }
}

// ---------------- main fused kernel: 4 warps x 2 batches, zero smem ----------------
__global__ void __launch_bounds__(NTH, 3)
tblock_kernel(const float* __restrict__ x,
              const float* __restrict__ bq, const float* __restrict__ bk,
              const float* __restrict__ bv, const float* __restrict__ bp,
              const float* __restrict__ b1, const float* __restrict__ b2,
              const float* __restrict__ g1, const float* __restrict__ be1,
              const float* __restrict__ g2, const float* __restrict__ be2,
              float* __restrict__ out) {
    const int tid  = threadIdx.x;
    const int lane = tid & 31;
    const int w    = tid >> 5;
    const int g0   = blockIdx.x * TOK;
    const int r    = lane >> 2, c2 = 2 * (lane & 3);
    const int row0[2] = { (2 * w) * 16 + r, (2 * w + 1) * 16 + r };

    // ---- load x in fragment layout; LN1 in registers ----
    uint32_t ah16[2][4][4];
#pragma unroll
    for (int bi = 0; bi < 2; ++bi) {
        float xv[8][4];
#pragma unroll
        for (int j = 0; j < 8; ++j) {
            int col = c2 + 8 * j;
            float2 xa = __ldg((const float2*)(x + (size_t)(g0 + row0[bi]) * 64 + col));
            float2 xb = __ldg((const float2*)(x + (size_t)(g0 + row0[bi] + 8) * 64 + col));
            xv[j][0] = xa.x; xv[j][1] = xa.y; xv[j][2] = xb.x; xv[j][3] = xb.y;
        }
        float s0 = 0.f, q0 = 0.f, s1 = 0.f, q1 = 0.f;
#pragma unroll
        for (int j = 0; j < 8; ++j) {
            s0 += xv[j][0] + xv[j][1];
            q0 += xv[j][0] * xv[j][0] + xv[j][1] * xv[j][1];
            s1 += xv[j][2] + xv[j][3];
            q1 += xv[j][2] * xv[j][2] + xv[j][3] * xv[j][3];
        }
        s0 += __shfl_xor_sync(0xffffffffu, s0, 1); s0 += __shfl_xor_sync(0xffffffffu, s0, 2);
        q0 += __shfl_xor_sync(0xffffffffu, q0, 1); q0 += __shfl_xor_sync(0xffffffffu, q0, 2);
        s1 += __shfl_xor_sync(0xffffffffu, s1, 1); s1 += __shfl_xor_sync(0xffffffffu, s1, 2);
        q1 += __shfl_xor_sync(0xffffffffu, q1, 1); q1 += __shfl_xor_sync(0xffffffffu, q1, 2);
        float mean0 = s0 * (1.f / 64.f), inv0 = rsqrtf(q0 * (1.f / 64.f) - mean0 * mean0 + EPSV);
        float mean1 = s1 * (1.f / 64.f), inv1 = rsqrtf(q1 * (1.f / 64.f) - mean1 * mean1 + EPSV);
#pragma unroll
        for (int j = 0; j < 8; ++j) {
            int col = c2 + 8 * j;
            float2 gg = __ldg((const float2*)(g1 + col));
            float2 bb = __ldg((const float2*)(be1 + col));
            xv[j][0] = (xv[j][0] - mean0) * inv0 * gg.x + bb.x;
            xv[j][1] = (xv[j][1] - mean0) * inv0 * gg.y + bb.y;
            xv[j][2] = (xv[j][2] - mean1) * inv1 * gg.x + bb.x;
            xv[j][3] = (xv[j][3] - mean1) * inv1 * gg.y + bb.y;
        }
        c2a(xv, ah16[bi]);
    }

    float pacc[2][8][4];                   // proj accumulator (registers)
#pragma unroll
    for (int j = 0; j < 8; ++j) {
        float2 bv2 = __ldg((const float2*)(bp + 8 * j + c2));
#pragma unroll
        for (int bi = 0; bi < 2; ++bi) {
            pacc[bi][j][0] = bv2.x; pacc[bi][j][1] = bv2.y;
            pacc[bi][j][2] = bv2.x; pacc[bi][j][3] = bv2.y;
        }
    }

    // ---- per-head attention, fb-streamed ----
#pragma unroll 1
    for (int h = 0; h < 4; ++h) {
        const uint4* wh = gWf + h * 2048;

        // S = Q K^T accumulated over feature blocks
        float S0[2][4], S1[2][4];
#pragma unroll
        for (int bi = 0; bi < 2; ++bi)
#pragma unroll
            for (int q = 0; q < 4; ++q) { S0[bi][q] = 0.f; S1[bi][q] = 0.f; }

#pragma unroll
        for (int fb = 0; fb < 4; ++fb) {
            float qt[2][2][4], kt[2][2][4];
            init8x2(qt, bq + h * 64 + fb * 16, c2);
            init8x2(kt, bk + h * 64 + fb * 16, c2);
            wgemm16c(ah16, wh, fb, lane, qt);
            wgemm16c(ah16, wh + 512, fb, lane, kt);
#pragma unroll
            for (int bi = 0; bi < 2; ++bi) {
                uint32_t qa[4], kb[4];
                qa[0] = h2u(qt[bi][0][0], qt[bi][0][1]);
                qa[1] = h2u(qt[bi][0][2], qt[bi][0][3]);
                qa[2] = h2u(qt[bi][1][0], qt[bi][1][1]);
                qa[3] = h2u(qt[bi][1][2], qt[bi][1][3]);
                kb[0] = h2u(kt[bi][0][0], kt[bi][0][1]);
                kb[1] = h2u(kt[bi][1][0], kt[bi][1][1]);
                kb[2] = h2u(kt[bi][0][2], kt[bi][0][3]);
                kb[3] = h2u(kt[bi][1][2], kt[bi][1][3]);
                mma16816(S0[bi], qa, &kb[0]);
                mma16816(S1[bi], qa, &kb[2]);
            }
        }

        // causal softmax -> aP per batch
        uint32_t aP[2][4];
#pragma unroll
        for (int bi = 0; bi < 2; ++bi) {
            float sc[2][4];
#pragma unroll
            for (int t = 0; t < 2; ++t) {
                const float* sv_ = t ? S1[bi] : S0[bi];
#pragma unroll
                for (int q = 0; q < 4; ++q) {
                    int row = r + ((q >> 1) * 8);
                    int col = 8 * t + c2 + (q & 1);
                    sc[t][q] = (col <= row) ? sv_[q] * SCL : -1e30f;
                }
            }
            float m0 = fmaxf(fmaxf(sc[0][0], sc[0][1]), fmaxf(sc[1][0], sc[1][1]));
            float m1 = fmaxf(fmaxf(sc[0][2], sc[0][3]), fmaxf(sc[1][2], sc[1][3]));
            m0 = fmaxf(m0, __shfl_xor_sync(0xffffffffu, m0, 1));
            m0 = fmaxf(m0, __shfl_xor_sync(0xffffffffu, m0, 2));
            m1 = fmaxf(m1, __shfl_xor_sync(0xffffffffu, m1, 1));
            m1 = fmaxf(m1, __shfl_xor_sync(0xffffffffu, m1, 2));
            float p[2][4];
            float sum0 = 0.f, sum1 = 0.f;
#pragma unroll
            for (int t = 0; t < 2; ++t) {
                p[t][0] = __expf(sc[t][0] - m0); p[t][1] = __expf(sc[t][1] - m0);
                p[t][2] = __expf(sc[t][2] - m1); p[t][3] = __expf(sc[t][3] - m1);
                sum0 += p[t][0] + p[t][1];
                sum1 += p[t][2] + p[t][3];
            }
            sum0 += __shfl_xor_sync(0xffffffffu, sum0, 1);
            sum0 += __shfl_xor_sync(0xffffffffu, sum0, 2);
            sum1 += __shfl_xor_sync(0xffffffffu, sum1, 1);
            sum1 += __shfl_xor_sync(0xffffffffu, sum1, 2);
            float i0 = 1.f / sum0, i1 = 1.f / sum1;
            aP[bi][0] = h2u(p[0][0] * i0, p[0][1] * i0);
            aP[bi][1] = h2u(p[0][2] * i1, p[0][3] * i1);
            aP[bi][2] = h2u(p[1][0] * i0, p[1][1] * i0);
            aP[bi][3] = h2u(p[1][2] * i1, p[1][3] * i1);
        }

        // V / ctx / proj streamed per feature block
#pragma unroll
        for (int fb = 0; fb < 4; ++fb) {
            float vt[2][2][4];
            init8x2(vt, bv + h * 64 + fb * 16, c2);
            wgemm16c(ah16, wh + 1024, fb, lane, vt);

            uint32_t ca[2][4];
#pragma unroll
            for (int bi = 0; bi < 2; ++bi) {
                uint32_t bb[2];
                float cc0[4] = {0.f, 0.f, 0.f, 0.f};
                float cc1[4] = {0.f, 0.f, 0.f, 0.f};
                bb[0] = movm(h2u(vt[bi][0][0], vt[bi][0][1]));
                bb[1] = movm(h2u(vt[bi][0][2], vt[bi][0][3]));
                mma16816(cc0, aP[bi], bb);
                bb[0] = movm(h2u(vt[bi][1][0], vt[bi][1][1]));
                bb[1] = movm(h2u(vt[bi][1][2], vt[bi][1][3]));
                mma16816(cc1, aP[bi], bb);
                ca[bi][0] = h2u(cc0[0], cc0[1]);
                ca[bi][1] = h2u(cc0[2], cc0[3]);
                ca[bi][2] = h2u(cc1[0], cc1[1]);
                ca[bi][3] = h2u(cc1[2], cc1[3]);
            }
            // pacc += ctx_fb @ Wp[k-step fb]
#pragma unroll
            for (int p = 0; p < 4; ++p) {
                uint4 q = __ldg(wh + 1536 + (fb * 4 + p) * 32 + lane);
                uint32_t bA[2] = {q.x, q.y}, bB[2] = {q.z, q.w};
#pragma unroll
                for (int bi = 0; bi < 2; ++bi) {
                    mma16816(pacc[bi][2 * p],     ca[bi], bA);
                    mma16816(pacc[bi][2 * p + 1], ca[bi], bB);
                }
            }
        }
    }

    // ---- x2 = x + pacc (x re-read from gmem); stash x2 in OUT; LN2 -> A2 frags ----
    uint32_t A2[2][4][4];
#pragma unroll
    for (int bi = 0; bi < 2; ++bi) {
        float x2v[8][4];
#pragma unroll
        for (int j = 0; j < 8; ++j) {
            int col = c2 + 8 * j;
            float2 xa = __ldg((const float2*)(x + (size_t)(g0 + row0[bi]) * 64 + col));
            float2 xb = __ldg((const float2*)(x + (size_t)(g0 + row0[bi] + 8) * 64 + col));
            x2v[j][0] = xa.x + pacc[bi][j][0]; x2v[j][1] = xa.y + pacc[bi][j][1];
            x2v[j][2] = xb.x + pacc[bi][j][2]; x2v[j][3] = xb.y + pacc[bi][j][3];
            *(float2*)(out + (size_t)(g0 + row0[bi]) * 64 + col) =
                make_float2(x2v[j][0], x2v[j][1]);
            *(float2*)(out + (size_t)(g0 + row0[bi] + 8) * 64 + col) =
                make_float2(x2v[j][2], x2v[j][3]);
        }
        float s0 = 0.f, q0 = 0.f, s1 = 0.f, q1 = 0.f;
#pragma unroll
        for (int j = 0; j < 8; ++j) {
            s0 += x2v[j][0] + x2v[j][1];
            q0 += x2v[j][0] * x2v[j][0] + x2v[j][1] * x2v[j][1];
            s1 += x2v[j][2] + x2v[j][3];
            q1 += x2v[j][2] * x2v[j][2] + x2v[j][3] * x2v[j][3];
        }
        s0 += __shfl_xor_sync(0xffffffffu, s0, 1); s0 += __shfl_xor_sync(0xffffffffu, s0, 2);
        q0 += __shfl_xor_sync(0xffffffffu, q0, 1); q0 += __shfl_xor_sync(0xffffffffu, q0, 2);
        s1 += __shfl_xor_sync(0xffffffffu, s1, 1); s1 += __shfl_xor_sync(0xffffffffu, s1, 2);
        q1 += __shfl_xor_sync(0xffffffffu, q1, 1); q1 += __shfl_xor_sync(0xffffffffu, q1, 2);
        float mean0 = s0 * (1.f / 64.f), inv0 = rsqrtf(q0 * (1.f / 64.f) - mean0 * mean0 + EPSV);
        float mean1 = s1 * (1.f / 64.f), inv1 = rsqrtf(q1 * (1.f / 64.f) - mean1 * mean1 + EPSV);
        float nv[8][4];
#pragma unroll
        for (int j = 0; j < 8; ++j) {
            int col = c2 + 8 * j;
            float2 gg = __ldg((const float2*)(g2 + col));
            float2 bb = __ldg((const float2*)(be2 + col));
            nv[j][0] = (x2v[j][0] - mean0) * inv0 * gg.x + bb.x;
            nv[j][1] = (x2v[j][1] - mean0) * inv0 * gg.y + bb.y;
            nv[j][2] = (x2v[j][2] - mean1) * inv1 * gg.x + bb.x;
            nv[j][3] = (x2v[j][3] - mean1) * inv1 * gg.y + bb.y;
        }
        c2a(nv, A2[bi]);
    }

    // ---- FFN: fb-streamed, oacc in registers ----
    float oacc[2][8][4];
#pragma unroll
    for (int j = 0; j < 8; ++j) {
        float2 bv2 = __ldg((const float2*)(b2 + 8 * j + c2));
#pragma unroll
        for (int bi = 0; bi < 2; ++bi) {
            oacc[bi][j][0] = bv2.x; oacc[bi][j][1] = bv2.y;
            oacc[bi][j][2] = bv2.x; oacc[bi][j][3] = bv2.y;
        }
    }
#pragma unroll 1
    for (int cc = 0; cc < 4; ++cc) {
        const uint4* w1c = gWf + (16 + cc) * 512;
        const uint4* w2c = gWf + (20 + cc) * 512;
#pragma unroll
        for (int fb = 0; fb < 4; ++fb) {
            float ht[2][2][4];
            init8x2(ht, b1 + cc * 64 + fb * 16, c2);
            wgemm16c(A2, w1c, fb, lane, ht);
            uint32_t ha[2][4];
#pragma unroll
            for (int bi = 0; bi < 2; ++bi) {
                ha[bi][0] = h2u(fmaxf(ht[bi][0][0], 0.f), fmaxf(ht[bi][0][1], 0.f));
                ha[bi][1] = h2u(fmaxf(ht[bi][0][2], 0.f), fmaxf(ht[bi][0][3], 0.f));
                ha[bi][2] = h2u(fmaxf(ht[bi][1][0], 0.f), fmaxf(ht[bi][1][1], 0.f));
                ha[bi][3] = h2u(fmaxf(ht[bi][1][2], 0.f), fmaxf(ht[bi][1][3], 0.f));
            }
#pragma unroll
            for (int p = 0; p < 4; ++p) {
                uint4 q = __ldg(w2c + (fb * 4 + p) * 32 + lane);
                uint32_t bA[2] = {q.x, q.y}, bB[2] = {q.z, q.w};
#pragma unroll
                for (int bi = 0; bi < 2; ++bi) {
                    mma16816(oacc[bi][2 * p],     ha[bi], bA);
                    mma16816(oacc[bi][2 * p + 1], ha[bi], bB);
                }
            }
        }
    }

    // ---- out = x2(in out) + ffn  (same-thread read-modify-write, program ordered) ----
#pragma unroll
    for (int bi = 0; bi < 2; ++bi)
#pragma unroll
        for (int j = 0; j < 8; ++j) {
            int col = c2 + 8 * j;
            float* oa = out + (size_t)(g0 + row0[bi]) * 64 + col;
            float* ob = out + (size_t)(g0 + row0[bi] + 8) * 64 + col;
            float2 xa = *(const float2*)oa;
            float2 xb = *(const float2*)ob;
            *(float2*)oa = make_float2(xa.x + oacc[bi][j][0], xa.y + oacc[bi][j][1]);
            *(float2*)ob = make_float2(xb.x + oacc[bi][j][2], xb.y + oacc[bi][j][3]);
        }
}

extern "C" void kernel_launch(void* const* d_in, const int* in_sizes, int n_in,
                              void* d_out, int out_size) {
    const float* x   = (const float*)d_in[0];
    const float* Wq  = (const float*)d_in[1];
    const float* bq  = (const float*)d_in[2];
    const float* Wk  = (const float*)d_in[3];
    const float* bk  = (const float*)d_in[4];
    const float* Wv  = (const float*)d_in[5];
    const float* bv  = (const float*)d_in[6];
    const float* Wp  = (const float*)d_in[7];
    const float* bp  = (const float*)d_in[8];
    const float* W1  = (const float*)d_in[9];
    const float* b1  = (const float*)d_in[10];
    const float* W2  = (const float*)d_in[11];
    const float* b2  = (const float*)d_in[12];
    const float* g1  = (const float*)d_in[13];
    const float* be1 = (const float*)d_in[14];
    const float* g2  = (const float*)d_in[15];
    const float* be2 = (const float*)d_in[16];
    float* out = (float*)d_out;

    pack_weights<<<24, 256>>>(Wq, Wk, Wv, Wp, W1, W2);

    dim3 grid(Bn / 8);   // 2048
    dim3 block(NTH);
    tblock_kernel<<<grid, block>>>(x, bq, bk, bv, bp, b1, b2,
                                   g1, be1, g2, be2, out);
}

// round 15
// speedup vs baseline: 1.1473x; 1.1473x over previous
#include <cuda_runtime.h>
#include <cuda_fp16.h>
#include <math.h>
#include <stdint.h>

#define Bn   16384
#define TOK  128          // tokens per CTA (8 batches; 2 per warp, 4 warps)
#define LDF  68           // float stride for x/x2 smem stash
#define NTH  128
#define EPSV 1e-5f
#define SCL  0.25f

// Weights pre-packed in b-fragment order: per 64x64 matrix, 512 uint4:
//   index = (ks*4 + nbp)*32 + lane ; uint4 = {b0,b1 of n-block 2*nbp ; b0,b1 of 2*nbp+1}
// Matrices: 0-15 head h*{Wq,Wk,Wv,Wp}; 16-19 W1 chunks; 20-23 W2 chunks
__device__ __align__(16) uint4 gWf[24 * 512];

// ---------------- PTX helpers ----------------
__device__ __forceinline__ void mma16816(float* d, const uint32_t* a, const uint32_t* b) {
    asm volatile("mma.sync.aligned.m16n8k16.row.col.f32.f16.f16.f32 "
                 "{%0,%1,%2,%3},{%4,%5,%6,%7},{%8,%9},{%0,%1,%2,%3};"
                 : "+f"(d[0]), "+f"(d[1]), "+f"(d[2]), "+f"(d[3])
                 : "r"(a[0]), "r"(a[1]), "r"(a[2]), "r"(a[3]), "r"(b[0]), "r"(b[1]));
}
// fp16-accumulator variant (2x throughput, packed D)
__device__ __forceinline__ void mma16816h(uint32_t* d, const uint32_t* a, const uint32_t* b) {
    asm volatile("mma.sync.aligned.m16n8k16.row.col.f16.f16.f16.f16 "
                 "{%0,%1},{%2,%3,%4,%5},{%6,%7},{%0,%1};"
                 : "+r"(d[0]), "+r"(d[1])
                 : "r"(a[0]), "r"(a[1]), "r"(a[2]), "r"(a[3]), "r"(b[0]), "r"(b[1]));
}
__device__ __forceinline__ uint32_t h2u(float a, float b) {
    __half2 h = __floats2half2_rn(a, b);
    return *(uint32_t*)&h;
}
__device__ __forceinline__ uint32_t movm(uint32_t s) {
    uint32_t d;
    asm volatile("movmatrix.sync.aligned.m8n8.trans.b16 %0, %1;" : "=r"(d) : "r"(s));
    return d;
}

// 16-col-block GEMM fp32-accum (2 batches)
__device__ __forceinline__ void wgemm16c(const uint32_t a[2][4][4],
                                         const uint4* __restrict__ wf, int fb,
                                         int lane, float acc[2][2][4]) {
#pragma unroll
    for (int ks = 0; ks < 4; ++ks) {
        uint4 q = __ldg(wf + (ks * 4 + fb) * 32 + lane);
        uint32_t bA[2] = {q.x, q.y}, bB[2] = {q.z, q.w};
#pragma unroll
        for (int bi = 0; bi < 2; ++bi) {
            mma16816(acc[bi][0], a[bi][ks], bA);
            mma16816(acc[bi][1], a[bi][ks], bB);
        }
    }
}
// 16-col-block GEMM fp16-accum (2 batches): acc[bi][tile][2 packed regs]
__device__ __forceinline__ void wgemm16ch(const uint32_t a[2][4][4],
                                          const uint4* __restrict__ wf, int fb,
                                          int lane, uint32_t acc[2][2][2]) {
#pragma unroll
    for (int ks = 0; ks < 4; ++ks) {
        uint4 q = __ldg(wf + (ks * 4 + fb) * 32 + lane);
        uint32_t bA[2] = {q.x, q.y}, bB[2] = {q.z, q.w};
#pragma unroll
        for (int bi = 0; bi < 2; ++bi) {
            mma16816h(acc[bi][0], a[bi][ks], bA);
            mma16816h(acc[bi][1], a[bi][ks], bB);
        }
    }
}
// bias init for a 16-col block (both batches), fp32 accum
__device__ __forceinline__ void init8x2(float acc[2][2][4], const float* bias16, int c2) {
#pragma unroll
    for (int j = 0; j < 2; ++j) {
        float2 bv = __ldg((const float2*)(bias16 + 8 * j + c2));
#pragma unroll
        for (int bi = 0; bi < 2; ++bi) {
            acc[bi][j][0] = bv.x; acc[bi][j][1] = bv.y;
            acc[bi][j][2] = bv.x; acc[bi][j][3] = bv.y;
        }
    }
}
// bias init, fp16-packed accum
__device__ __forceinline__ void init8x2h(uint32_t acc[2][2][2], const float* bias16, int c2) {
#pragma unroll
    for (int j = 0; j < 2; ++j) {
        float2 bv = __ldg((const float2*)(bias16 + 8 * j + c2));
        uint32_t p = h2u(bv.x, bv.y);
#pragma unroll
        for (int bi = 0; bi < 2; ++bi) {
            acc[bi][j][0] = p;   // row r
            acc[bi][j][1] = p;   // row r+8
        }
    }
}
// full-width C-fragment (fp32, 16x64) -> A-fragment (half2)
__device__ __forceinline__ void c2a(const float cc[8][4], uint32_t a[4][4]) {
#pragma unroll
    for (int ks = 0; ks < 4; ++ks) {
#pragma unroll
        for (int t = 0; t < 2; ++t) {
            a[ks][2 * t]     = h2u(cc[2 * ks + t][0], cc[2 * ks + t][1]);
            a[ks][2 * t + 1] = h2u(cc[2 * ks + t][2], cc[2 * ks + t][3]);
        }
    }
}

// ---------------- weight pack: fp32 -> fp16 b-fragment order ----------------
__global__ void pack_weights(const float* __restrict__ Wq, const float* __restrict__ Wk,
                             const float* __restrict__ Wv, const float* __restrict__ Wp,
                             const float* __restrict__ W1, const float* __restrict__ W2) {
    int m = blockIdx.x, tid = threadIdx.x;
    const float* src;
    int stride;
    if (m < 16) {
        int h = m >> 2, t = m & 3;
        const float* w = (t == 0) ? Wq : (t == 1) ? Wk : (t == 2) ? Wv : Wp;
        src = w + h * 4096; stride = 64;
    } else if (m < 20) {
        src = W1 + (m - 16) * 64; stride = 256;   // W1[:, cc*64 .. +63]
    } else {
        src = W2 + (m - 20) * 4096; stride = 64;  // W2[cc*64 .. +63, :]
    }
    for (int idx = tid; idx < 512; idx += 256) {
        int lane = idx & 31, nbp = (idx >> 5) & 3, ks = idx >> 7;
        int c = lane & 3, r = lane >> 2;
        int kb = ks * 16 + 2 * c;
        int n0 = nbp * 16 + r, n1 = n0 + 8;
        uint4 q;
        q.x = h2u(src[kb * stride + n0],       src[(kb + 1) * stride + n0]);
        q.y = h2u(src[(kb + 8) * stride + n0], src[(kb + 9) * stride + n0]);
        q.z = h2u(src[kb * stride + n1],       src[(kb + 1) * stride + n1]);
        q.w = h2u(src[(kb + 8) * stride + n1], src[(kb + 9) * stride + n1]);
        gWf[m * 512 + idx] = q;
    }
}

// ---------------- main fused kernel: 4 warps x 2 batches, fb-streamed -----------------
__global__ void __launch_bounds__(NTH, 3)
tblock_kernel(const float* __restrict__ x,
              const float* __restrict__ bq, const float* __restrict__ bk,
              const float* __restrict__ bv, const float* __restrict__ bp,
              const float* __restrict__ b1, const float* __restrict__ b2,
              const float* __restrict__ g1, const float* __restrict__ be1,
              const float* __restrict__ g2, const float* __restrict__ be2,
              float* __restrict__ out) {
    extern __shared__ __align__(16) float xs[];   // TOK x LDF : raw x, later x2

    const int tid  = threadIdx.x;
    const int lane = tid & 31;
    const int w    = tid >> 5;
    const int g0   = blockIdx.x * TOK;
    const int r    = lane >> 2, c2 = 2 * (lane & 3);
    const int row0[2] = { (2 * w) * 16 + r, (2 * w + 1) * 16 + r };

    // ---- load x in fragment layout + stash raw to smem; LN1 in registers ----
    uint32_t ah16[2][4][4];
#pragma unroll
    for (int bi = 0; bi < 2; ++bi) {
        float xv[8][4];
#pragma unroll
        for (int j = 0; j < 8; ++j) {
            int col = c2 + 8 * j;
            float2 xa = __ldg((const float2*)(x + (size_t)(g0 + row0[bi]) * 64 + col));
            float2 xb = __ldg((const float2*)(x + (size_t)(g0 + row0[bi] + 8) * 64 + col));
            xv[j][0] = xa.x; xv[j][1] = xa.y; xv[j][2] = xb.x; xv[j][3] = xb.y;
            *(float2*)(xs + row0[bi] * LDF + col)       = xa;
            *(float2*)(xs + (row0[bi] + 8) * LDF + col) = xb;
        }
        float s0 = 0.f, q0 = 0.f, s1 = 0.f, q1 = 0.f;
#pragma unroll
        for (int j = 0; j < 8; ++j) {
            s0 += xv[j][0] + xv[j][1];
            q0 += xv[j][0] * xv[j][0] + xv[j][1] * xv[j][1];
            s1 += xv[j][2] + xv[j][3];
            q1 += xv[j][2] * xv[j][2] + xv[j][3] * xv[j][3];
        }
        s0 += __shfl_xor_sync(0xffffffffu, s0, 1); s0 += __shfl_xor_sync(0xffffffffu, s0, 2);
        q0 += __shfl_xor_sync(0xffffffffu, q0, 1); q0 += __shfl_xor_sync(0xffffffffu, q0, 2);
        s1 += __shfl_xor_sync(0xffffffffu, s1, 1); s1 += __shfl_xor_sync(0xffffffffu, s1, 2);
        q1 += __shfl_xor_sync(0xffffffffu, q1, 1); q1 += __shfl_xor_sync(0xffffffffu, q1, 2);
        float mean0 = s0 * (1.f / 64.f), inv0 = rsqrtf(q0 * (1.f / 64.f) - mean0 * mean0 + EPSV);
        float mean1 = s1 * (1.f / 64.f), inv1 = rsqrtf(q1 * (1.f / 64.f) - mean1 * mean1 + EPSV);
#pragma unroll
        for (int j = 0; j < 8; ++j) {
            int col = c2 + 8 * j;
            float2 gg = __ldg((const float2*)(g1 + col));
            float2 bb = __ldg((const float2*)(be1 + col));
            xv[j][0] = (xv[j][0] - mean0) * inv0 * gg.x + bb.x;
            xv[j][1] = (xv[j][1] - mean0) * inv0 * gg.y + bb.y;
            xv[j][2] = (xv[j][2] - mean1) * inv1 * gg.x + bb.x;
            xv[j][3] = (xv[j][3] - mean1) * inv1 * gg.y + bb.y;
        }
        c2a(xv, ah16[bi]);
    }

    float pacc[2][8][4];                   // proj accumulator (registers, fp32)
#pragma unroll
    for (int j = 0; j < 8; ++j) {
        float2 bv2 = __ldg((const float2*)(bp + 8 * j + c2));
#pragma unroll
        for (int bi = 0; bi < 2; ++bi) {
            pacc[bi][j][0] = bv2.x; pacc[bi][j][1] = bv2.y;
            pacc[bi][j][2] = bv2.x; pacc[bi][j][3] = bv2.y;
        }
    }

    // ---- per-head attention, fb-streamed; Q/K GEMMs in fp16-accum ----
#pragma unroll 1
    for (int h = 0; h < 4; ++h) {
        const uint4* wh = gWf + h * 2048;

        // S = Q K^T accumulated over feature blocks (fp32)
        float S0[2][4], S1[2][4];
#pragma unroll
        for (int bi = 0; bi < 2; ++bi)
#pragma unroll
            for (int q = 0; q < 4; ++q) { S0[bi][q] = 0.f; S1[bi][q] = 0.f; }

#pragma unroll
        for (int fb = 0; fb < 4; ++fb) {
            // Q, K in fp16-accum: D fragments ARE the a/b fragments (no repack)
            uint32_t qt[2][2][2], kt[2][2][2];
            init8x2h(qt, bq + h * 64 + fb * 16, c2);
            init8x2h(kt, bk + h * 64 + fb * 16, c2);
            wgemm16ch(ah16, wh, fb, lane, qt);
            wgemm16ch(ah16, wh + 512, fb, lane, kt);
#pragma unroll
            for (int bi = 0; bi < 2; ++bi) {
                uint32_t qa[4], kb[4];
                qa[0] = qt[bi][0][0];   // row r,  k 0-7 block of this fb
                qa[1] = qt[bi][0][1];   // row r+8
                qa[2] = qt[bi][1][0];   // row r,  k 8-15
                qa[3] = qt[bi][1][1];   // row r+8
                kb[0] = kt[bi][0][0];   // keys 0-7  (tile0)
                kb[1] = kt[bi][1][0];   //           (tile1)
                kb[2] = kt[bi][0][1];   // keys 8-15
                kb[3] = kt[bi][1][1];
                mma16816(S0[bi], qa, &kb[0]);
                mma16816(S1[bi], qa, &kb[2]);
            }
        }

        // causal softmax -> aP per batch
        uint32_t aP[2][4];
#pragma unroll
        for (int bi = 0; bi < 2; ++bi) {
            float sc[2][4];
#pragma unroll
            for (int t = 0; t < 2; ++t) {
                const float* sv_ = t ? S1[bi] : S0[bi];
#pragma unroll
                for (int q = 0; q < 4; ++q) {
                    int row = r + ((q >> 1) * 8);
                    int col = 8 * t + c2 + (q & 1);
                    sc[t][q] = (col <= row) ? sv_[q] * SCL : -1e30f;
                }
            }
            float m0 = fmaxf(fmaxf(sc[0][0], sc[0][1]), fmaxf(sc[1][0], sc[1][1]));
            float m1 = fmaxf(fmaxf(sc[0][2], sc[0][3]), fmaxf(sc[1][2], sc[1][3]));
            m0 = fmaxf(m0, __shfl_xor_sync(0xffffffffu, m0, 1));
            m0 = fmaxf(m0, __shfl_xor_sync(0xffffffffu, m0, 2));
            m1 = fmaxf(m1, __shfl_xor_sync(0xffffffffu, m1, 1));
            m1 = fmaxf(m1, __shfl_xor_sync(0xffffffffu, m1, 2));
            float p[2][4];
            float sum0 = 0.f, sum1 = 0.f;
#pragma unroll
            for (int t = 0; t < 2; ++t) {
                p[t][0] = __expf(sc[t][0] - m0); p[t][1] = __expf(sc[t][1] - m0);
                p[t][2] = __expf(sc[t][2] - m1); p[t][3] = __expf(sc[t][3] - m1);
                sum0 += p[t][0] + p[t][1];
                sum1 += p[t][2] + p[t][3];
            }
            sum0 += __shfl_xor_sync(0xffffffffu, sum0, 1);
            sum0 += __shfl_xor_sync(0xffffffffu, sum0, 2);
            sum1 += __shfl_xor_sync(0xffffffffu, sum1, 1);
            sum1 += __shfl_xor_sync(0xffffffffu, sum1, 2);
            float i0 = 1.f / sum0, i1 = 1.f / sum1;
            aP[bi][0] = h2u(p[0][0] * i0, p[0][1] * i0);
            aP[bi][1] = h2u(p[0][2] * i1, p[0][3] * i1);
            aP[bi][2] = h2u(p[1][0] * i0, p[1][1] * i0);
            aP[bi][3] = h2u(p[1][2] * i1, p[1][3] * i1);
        }

        // V / ctx / proj streamed per feature block (fp32 accum)
#pragma unroll
        for (int fb = 0; fb < 4; ++fb) {
            float vt[2][2][4];
            init8x2(vt, bv + h * 64 + fb * 16, c2);
            wgemm16c(ah16, wh + 1024, fb, lane, vt);

            uint32_t ca[2][4];
#pragma unroll
            for (int bi = 0; bi < 2; ++bi) {
                uint32_t bb[2];
                float cc0[4] = {0.f, 0.f, 0.f, 0.f};
                float cc1[4] = {0.f, 0.f, 0.f, 0.f};
                bb[0] = movm(h2u(vt[bi][0][0], vt[bi][0][1]));
                bb[1] = movm(h2u(vt[bi][0][2], vt[bi][0][3]));
                mma16816(cc0, aP[bi], bb);
                bb[0] = movm(h2u(vt[bi][1][0], vt[bi][1][1]));
                bb[1] = movm(h2u(vt[bi][1][2], vt[bi][1][3]));
                mma16816(cc1, aP[bi], bb);
                ca[bi][0] = h2u(cc0[0], cc0[1]);
                ca[bi][1] = h2u(cc0[2], cc0[3]);
                ca[bi][2] = h2u(cc1[0], cc1[1]);
                ca[bi][3] = h2u(cc1[2], cc1[3]);
            }
            // pacc += ctx_fb @ Wp[k-step fb]
#pragma unroll
            for (int p = 0; p < 4; ++p) {
                uint4 q = __ldg(wh + 1536 + (fb * 4 + p) * 32 + lane);
                uint32_t bA[2] = {q.x, q.y}, bB[2] = {q.z, q.w};
#pragma unroll
                for (int bi = 0; bi < 2; ++bi) {
                    mma16816(pacc[bi][2 * p],     ca[bi], bA);
                    mma16816(pacc[bi][2 * p + 1], ca[bi], bB);
                }
            }
        }
    }

    // ---- x2 = x + pacc; stash; LN2 in registers -> A2 frags ----
    uint32_t A2[2][4][4];
#pragma unroll
    for (int bi = 0; bi < 2; ++bi) {
        float x2v[8][4];
#pragma unroll
        for (int j = 0; j < 8; ++j) {
            int col = c2 + 8 * j;
            float2 xa = *(const float2*)(xs + row0[bi] * LDF + col);
            float2 xb = *(const float2*)(xs + (row0[bi] + 8) * LDF + col);
            x2v[j][0] = xa.x + pacc[bi][j][0]; x2v[j][1] = xa.y + pacc[bi][j][1];
            x2v[j][2] = xb.x + pacc[bi][j][2]; x2v[j][3] = xb.y + pacc[bi][j][3];
            *(float2*)(xs + row0[bi] * LDF + col)       = make_float2(x2v[j][0], x2v[j][1]);
            *(float2*)(xs + (row0[bi] + 8) * LDF + col) = make_float2(x2v[j][2], x2v[j][3]);
        }
        float s0 = 0.f, q0 = 0.f, s1 = 0.f, q1 = 0.f;
#pragma unroll
        for (int j = 0; j < 8; ++j) {
            s0 += x2v[j][0] + x2v[j][1];
            q0 += x2v[j][0] * x2v[j][0] + x2v[j][1] * x2v[j][1];
            s1 += x2v[j][2] + x2v[j][3];
            q1 += x2v[j][2] * x2v[j][2] + x2v[j][3] * x2v[j][3];
        }
        s0 += __shfl_xor_sync(0xffffffffu, s0, 1); s0 += __shfl_xor_sync(0xffffffffu, s0, 2);
        q0 += __shfl_xor_sync(0xffffffffu, q0, 1); q0 += __shfl_xor_sync(0xffffffffu, q0, 2);
        s1 += __shfl_xor_sync(0xffffffffu, s1, 1); s1 += __shfl_xor_sync(0xffffffffu, s1, 2);
        q1 += __shfl_xor_sync(0xffffffffu, q1, 1); q1 += __shfl_xor_sync(0xffffffffu, q1, 2);
        float mean0 = s0 * (1.f / 64.f), inv0 = rsqrtf(q0 * (1.f / 64.f) - mean0 * mean0 + EPSV);
        float mean1 = s1 * (1.f / 64.f), inv1 = rsqrtf(q1 * (1.f / 64.f) - mean1 * mean1 + EPSV);
        float nv[8][4];
#pragma unroll
        for (int j = 0; j < 8; ++j) {
            int col = c2 + 8 * j;
            float2 gg = __ldg((const float2*)(g2 + col));
            float2 bb = __ldg((const float2*)(be2 + col));
            nv[j][0] = (x2v[j][0] - mean0) * inv0 * gg.x + bb.x;
            nv[j][1] = (x2v[j][1] - mean0) * inv0 * gg.y + bb.y;
            nv[j][2] = (x2v[j][2] - mean1) * inv1 * gg.x + bb.x;
            nv[j][3] = (x2v[j][3] - mean1) * inv1 * gg.y + bb.y;
        }
        c2a(nv, A2[bi]);
    }

    // ---- FFN: fb-streamed, fp32 accum, oacc in registers ----
    float oacc[2][8][4];
#pragma unroll
    for (int j = 0; j < 8; ++j) {
        float2 bv2 = __ldg((const float2*)(b2 + 8 * j + c2));
#pragma unroll
        for (int bi = 0; bi < 2; ++bi) {
            oacc[bi][j][0] = bv2.x; oacc[bi][j][1] = bv2.y;
            oacc[bi][j][2] = bv2.x; oacc[bi][j][3] = bv2.y;
        }
    }
#pragma unroll 1
    for (int cc = 0; cc < 4; ++cc) {
        const uint4* w1c = gWf + (16 + cc) * 512;
        const uint4* w2c = gWf + (20 + cc) * 512;
#pragma unroll
        for (int fb = 0; fb < 4; ++fb) {
            float ht[2][2][4];
            init8x2(ht, b1 + cc * 64 + fb * 16, c2);
            wgemm16c(A2, w1c, fb, lane, ht);
            uint32_t ha[2][4];
#pragma unroll
            for (int bi = 0; bi < 2; ++bi) {
                ha[bi][0] = h2u(fmaxf(ht[bi][0][0], 0.f), fmaxf(ht[bi][0][1], 0.f));
                ha[bi][1] = h2u(fmaxf(ht[bi][0][2], 0.f), fmaxf(ht[bi][0][3], 0.f));
                ha[bi][2] = h2u(fmaxf(ht[bi][1][0], 0.f), fmaxf(ht[bi][1][1], 0.f));
                ha[bi][3] = h2u(fmaxf(ht[bi][1][2], 0.f), fmaxf(ht[bi][1][3], 0.f));
            }
#pragma unroll
            for (int p = 0; p < 4; ++p) {
                uint4 q = __ldg(w2c + (fb * 4 + p) * 32 + lane);
                uint32_t bA[2] = {q.x, q.y}, bB[2] = {q.z, q.w};
#pragma unroll
                for (int bi = 0; bi < 2; ++bi) {
                    mma16816(oacc[bi][2 * p],     ha[bi], bA);
                    mma16816(oacc[bi][2 * p + 1], ha[bi], bB);
                }
            }
        }
    }

    // ---- out = x2 + ffn ----
#pragma unroll
    for (int bi = 0; bi < 2; ++bi)
#pragma unroll
        for (int j = 0; j < 8; ++j) {
            int col = c2 + 8 * j;
            float2 xa = *(const float2*)(xs + row0[bi] * LDF + col);
            float2 xb = *(const float2*)(xs + (row0[bi] + 8) * LDF + col);
            *(float2*)(out + (size_t)(g0 + row0[bi]) * 64 + col) =
                make_float2(xa.x + oacc[bi][j][0], xa.y + oacc[bi][j][1]);
            *(float2*)(out + (size_t)(g0 + row0[bi] + 8) * 64 + col) =
                make_float2(xb.x + oacc[bi][j][2], xb.y + oacc[bi][j][3]);
        }
}

extern "C" void kernel_launch(void* const* d_in, const int* in_sizes, int n_in,
                              void* d_out, int out_size) {
    const float* x   = (const float*)d_in[0];
    const float* Wq  = (const float*)d_in[1];
    const float* bq  = (const float*)d_in[2];
    const float* Wk  = (const float*)d_in[3];
    const float* bk  = (const float*)d_in[4];
    const float* Wv  = (const float*)d_in[5];
    const float* bv  = (const float*)d_in[6];
    const float* Wp  = (const float*)d_in[7];
    const float* bp  = (const float*)d_in[8];
    const float* W1  = (const float*)d_in[9];
    const float* b1  = (const float*)d_in[10];
    const float* W2  = (const float*)d_in[11];
    const float* b2  = (const float*)d_in[12];
    const float* g1  = (const float*)d_in[13];
    const float* be1 = (const float*)d_in[14];
    const float* g2  = (const float*)d_in[15];
    const float* be2 = (const float*)d_in[16];
    float* out = (float*)d_out;

    pack_weights<<<24, 256>>>(Wq, Wk, Wv, Wp, W1, W2);

    const int smem_bytes = TOK * LDF * (int)sizeof(float);   // 34816
    cudaFuncSetAttribute(tblock_kernel, cudaFuncAttributeMaxDynamicSharedMemorySize, smem_bytes);

    dim3 grid(Bn / 8);   // 2048
    dim3 block(NTH);
    tblock_kernel<<<grid, block, smem_bytes>>>(x, bq, bk, bv, bp, b1, b2,
                                               g1, be1, g2, be2, out);
}

// round 16
// speedup vs baseline: 1.2322x; 1.0740x over previous
#include <cuda_runtime.h>
#include <cuda_fp16.h>
#include <math.h>
#include <stdint.h>

#define Bn   16384
#define TOK  128          // tokens per CTA (8 batches; 2 per warp, 4 warps)
#define LDF  68           // float stride for x/x2 smem stash
#define NTH  128
#define EPSV 1e-5f
#define SCL  0.25f

// Weights pre-packed in b-fragment order: per 64x64 matrix, 512 uint4:
//   index = (ks*4 + nbp)*32 + lane ; uint4 = {b0,b1 of n-block 2*nbp ; b0,b1 of 2*nbp+1}
// Matrices: 0-15 head h*{Wq,Wk,Wv,Wp}; 16-19 W1 chunks; 20-23 W2 chunks
__device__ __align__(16) uint4 gWf[24 * 512];

// ---------------- PTX helpers ----------------
__device__ __forceinline__ void mma16816(float* d, const uint32_t* a, const uint32_t* b) {
    asm volatile("mma.sync.aligned.m16n8k16.row.col.f32.f16.f16.f32 "
                 "{%0,%1,%2,%3},{%4,%5,%6,%7},{%8,%9},{%0,%1,%2,%3};"
                 : "+f"(d[0]), "+f"(d[1]), "+f"(d[2]), "+f"(d[3])
                 : "r"(a[0]), "r"(a[1]), "r"(a[2]), "r"(a[3]), "r"(b[0]), "r"(b[1]));
}
// fp16-accumulator variant (2x throughput, packed D)
__device__ __forceinline__ void mma16816h(uint32_t* d, const uint32_t* a, const uint32_t* b) {
    asm volatile("mma.sync.aligned.m16n8k16.row.col.f16.f16.f16.f16 "
                 "{%0,%1},{%2,%3,%4,%5},{%6,%7},{%0,%1};"
                 : "+r"(d[0]), "+r"(d[1])
                 : "r"(a[0]), "r"(a[1]), "r"(a[2]), "r"(a[3]), "r"(b[0]), "r"(b[1]));
}
__device__ __forceinline__ uint32_t h2u(float a, float b) {
    __half2 h = __floats2half2_rn(a, b);
    return *(uint32_t*)&h;
}
__device__ __forceinline__ uint32_t movm(uint32_t s) {
    uint32_t d;
    asm volatile("movmatrix.sync.aligned.m8n8.trans.b16 %0, %1;" : "=r"(d) : "r"(s));
    return d;
}
__device__ __forceinline__ uint32_t relu2(uint32_t v) {
    __half2 h = *(__half2*)&v;
    h = __hmax2(h, __float2half2_rn(0.f));
    return *(uint32_t*)&h;
}

// 16-col-block GEMM fp32-accum (2 batches)
__device__ __forceinline__ void wgemm16c(const uint32_t a[2][4][4],
                                         const uint4* __restrict__ wf, int fb,
                                         int lane, float acc[2][2][4]) {
#pragma unroll
    for (int ks = 0; ks < 4; ++ks) {
        uint4 q = __ldg(wf + (ks * 4 + fb) * 32 + lane);
        uint32_t bA[2] = {q.x, q.y}, bB[2] = {q.z, q.w};
#pragma unroll
        for (int bi = 0; bi < 2; ++bi) {
            mma16816(acc[bi][0], a[bi][ks], bA);
            mma16816(acc[bi][1], a[bi][ks], bB);
        }
    }
}
// 16-col-block GEMM fp16-accum (2 batches): acc[bi][tile][2 packed regs]
__device__ __forceinline__ void wgemm16ch(const uint32_t a[2][4][4],
                                          const uint4* __restrict__ wf, int fb,
                                          int lane, uint32_t acc[2][2][2]) {
#pragma unroll
    for (int ks = 0; ks < 4; ++ks) {
        uint4 q = __ldg(wf + (ks * 4 + fb) * 32 + lane);
        uint32_t bA[2] = {q.x, q.y}, bB[2] = {q.z, q.w};
#pragma unroll
        for (int bi = 0; bi < 2; ++bi) {
            mma16816h(acc[bi][0], a[bi][ks], bA);
            mma16816h(acc[bi][1], a[bi][ks], bB);
        }
    }
}
// bias init, fp16-packed accum
__device__ __forceinline__ void init8x2h(uint32_t acc[2][2][2], const float* bias16, int c2) {
#pragma unroll
    for (int j = 0; j < 2; ++j) {
        float2 bv = __ldg((const float2*)(bias16 + 8 * j + c2));
        uint32_t p = h2u(bv.x, bv.y);
#pragma unroll
        for (int bi = 0; bi < 2; ++bi) {
            acc[bi][j][0] = p;   // row r
            acc[bi][j][1] = p;   // row r+8
        }
    }
}
// full-width C-fragment (fp32, 16x64) -> A-fragment (half2)
__device__ __forceinline__ void c2a(const float cc[8][4], uint32_t a[4][4]) {
#pragma unroll
    for (int ks = 0; ks < 4; ++ks) {
#pragma unroll
        for (int t = 0; t < 2; ++t) {
            a[ks][2 * t]     = h2u(cc[2 * ks + t][0], cc[2 * ks + t][1]);
            a[ks][2 * t + 1] = h2u(cc[2 * ks + t][2], cc[2 * ks + t][3]);
        }
    }
}

// ---------------- weight pack: fp32 -> fp16 b-fragment order ----------------
__global__ void pack_weights(const float* __restrict__ Wq, const float* __restrict__ Wk,
                             const float* __restrict__ Wv, const float* __restrict__ Wp,
                             const float* __restrict__ W1, const float* __restrict__ W2) {
    int m = blockIdx.x, tid = threadIdx.x;
    const float* src;
    int stride;
    if (m < 16) {
        int h = m >> 2, t = m & 3;
        const float* w = (t == 0) ? Wq : (t == 1) ? Wk : (t == 2) ? Wv : Wp;
        src = w + h * 4096; stride = 64;
    } else if (m < 20) {
        src = W1 + (m - 16) * 64; stride = 256;   // W1[:, cc*64 .. +63]
    } else {
        src = W2 + (m - 20) * 4096; stride = 64;  // W2[cc*64 .. +63, :]
    }
    for (int idx = tid; idx < 512; idx += 256) {
        int lane = idx & 31, nbp = (idx >> 5) & 3, ks = idx >> 7;
        int c = lane & 3, r = lane >> 2;
        int kb = ks * 16 + 2 * c;
        int n0 = nbp * 16 + r, n1 = n0 + 8;
        uint4 q;
        q.x = h2u(src[kb * stride + n0],       src[(kb + 1) * stride + n0]);
        q.y = h2u(src[(kb + 8) * stride + n0], src[(kb + 9) * stride + n0]);
        q.z = h2u(src[kb * stride + n1],       src[(kb + 1) * stride + n1]);
        q.w = h2u(src[(kb + 8) * stride + n1], src[(kb + 9) * stride + n1]);
        gWf[m * 512 + idx] = q;
    }
}

// ---------------- main fused kernel: 4 warps x 2 batches, fb-streamed -----------------
__global__ void __launch_bounds__(NTH, 3)
tblock_kernel(const float* __restrict__ x,
              const float* __restrict__ bq, const float* __restrict__ bk,
              const float* __restrict__ bv, const float* __restrict__ bp,
              const float* __restrict__ b1, const float* __restrict__ b2,
              const float* __restrict__ g1, const float* __restrict__ be1,
              const float* __restrict__ g2, const float* __restrict__ be2,
              float* __restrict__ out) {
    extern __shared__ __align__(16) float xs[];   // TOK x LDF : raw x, later x2

    const int tid  = threadIdx.x;
    const int lane = tid & 31;
    const int w    = tid >> 5;
    const int g0   = blockIdx.x * TOK;
    const int r    = lane >> 2, c2 = 2 * (lane & 3);
    const int row0[2] = { (2 * w) * 16 + r, (2 * w + 1) * 16 + r };

    // ---- load x in fragment layout + stash raw to smem; LN1 in registers ----
    uint32_t ah16[2][4][4];
#pragma unroll
    for (int bi = 0; bi < 2; ++bi) {
        float xv[8][4];
#pragma unroll
        for (int j = 0; j < 8; ++j) {
            int col = c2 + 8 * j;
            float2 xa = __ldg((const float2*)(x + (size_t)(g0 + row0[bi]) * 64 + col));
            float2 xb = __ldg((const float2*)(x + (size_t)(g0 + row0[bi] + 8) * 64 + col));
            xv[j][0] = xa.x; xv[j][1] = xa.y; xv[j][2] = xb.x; xv[j][3] = xb.y;
            *(float2*)(xs + row0[bi] * LDF + col)       = xa;
            *(float2*)(xs + (row0[bi] + 8) * LDF + col) = xb;
        }
        float s0 = 0.f, q0 = 0.f, s1 = 0.f, q1 = 0.f;
#pragma unroll
        for (int j = 0; j < 8; ++j) {
            s0 += xv[j][0] + xv[j][1];
            q0 += xv[j][0] * xv[j][0] + xv[j][1] * xv[j][1];
            s1 += xv[j][2] + xv[j][3];
            q1 += xv[j][2] * xv[j][2] + xv[j][3] * xv[j][3];
        }
        s0 += __shfl_xor_sync(0xffffffffu, s0, 1); s0 += __shfl_xor_sync(0xffffffffu, s0, 2);
        q0 += __shfl_xor_sync(0xffffffffu, q0, 1); q0 += __shfl_xor_sync(0xffffffffu, q0, 2);
        s1 += __shfl_xor_sync(0xffffffffu, s1, 1); s1 += __shfl_xor_sync(0xffffffffu, s1, 2);
        q1 += __shfl_xor_sync(0xffffffffu, q1, 1); q1 += __shfl_xor_sync(0xffffffffu, q1, 2);
        float mean0 = s0 * (1.f / 64.f), inv0 = rsqrtf(q0 * (1.f / 64.f) - mean0 * mean0 + EPSV);
        float mean1 = s1 * (1.f / 64.f), inv1 = rsqrtf(q1 * (1.f / 64.f) - mean1 * mean1 + EPSV);
#pragma unroll
        for (int j = 0; j < 8; ++j) {
            int col = c2 + 8 * j;
            float2 gg = __ldg((const float2*)(g1 + col));
            float2 bb = __ldg((const float2*)(be1 + col));
            xv[j][0] = (xv[j][0] - mean0) * inv0 * gg.x + bb.x;
            xv[j][1] = (xv[j][1] - mean0) * inv0 * gg.y + bb.y;
            xv[j][2] = (xv[j][2] - mean1) * inv1 * gg.x + bb.x;
            xv[j][3] = (xv[j][3] - mean1) * inv1 * gg.y + bb.y;
        }
        c2a(xv, ah16[bi]);
    }

    float pacc[2][8][4];                   // proj accumulator (registers, fp32)
#pragma unroll
    for (int j = 0; j < 8; ++j) {
        float2 bv2 = __ldg((const float2*)(bp + 8 * j + c2));
#pragma unroll
        for (int bi = 0; bi < 2; ++bi) {
            pacc[bi][j][0] = bv2.x; pacc[bi][j][1] = bv2.y;
            pacc[bi][j][2] = bv2.x; pacc[bi][j][3] = bv2.y;
        }
    }

    // ---- per-head attention, fb-streamed; Q/K/V/ctx GEMMs in fp16-accum ----
#pragma unroll 1
    for (int h = 0; h < 4; ++h) {
        const uint4* wh = gWf + h * 2048;

        // S = Q K^T accumulated over feature blocks (fp32)
        float S0[2][4], S1[2][4];
#pragma unroll
        for (int bi = 0; bi < 2; ++bi)
#pragma unroll
            for (int q = 0; q < 4; ++q) { S0[bi][q] = 0.f; S1[bi][q] = 0.f; }

#pragma unroll
        for (int fb = 0; fb < 4; ++fb) {
            // Q, K in fp16-accum: D fragments ARE the a/b fragments (no repack)
            uint32_t qt[2][2][2], kt[2][2][2];
            init8x2h(qt, bq + h * 64 + fb * 16, c2);
            init8x2h(kt, bk + h * 64 + fb * 16, c2);
            wgemm16ch(ah16, wh, fb, lane, qt);
            wgemm16ch(ah16, wh + 512, fb, lane, kt);
#pragma unroll
            for (int bi = 0; bi < 2; ++bi) {
                uint32_t qa[4], kb[4];
                qa[0] = qt[bi][0][0];   // row r,  k 0-7 of this fb
                qa[1] = qt[bi][0][1];   // row r+8
                qa[2] = qt[bi][1][0];   // row r,  k 8-15
                qa[3] = qt[bi][1][1];   // row r+8
                kb[0] = kt[bi][0][0];   // keys 0-7
                kb[1] = kt[bi][1][0];
                kb[2] = kt[bi][0][1];   // keys 8-15
                kb[3] = kt[bi][1][1];
                mma16816(S0[bi], qa, &kb[0]);
                mma16816(S1[bi], qa, &kb[2]);
            }
        }

        // causal softmax -> aP per batch
        uint32_t aP[2][4];
#pragma unroll
        for (int bi = 0; bi < 2; ++bi) {
            float sc[2][4];
#pragma unroll
            for (int t = 0; t < 2; ++t) {
                const float* sv_ = t ? S1[bi] : S0[bi];
#pragma unroll
                for (int q = 0; q < 4; ++q) {
                    int row = r + ((q >> 1) * 8);
                    int col = 8 * t + c2 + (q & 1);
                    sc[t][q] = (col <= row) ? sv_[q] * SCL : -1e30f;
                }
            }
            float m0 = fmaxf(fmaxf(sc[0][0], sc[0][1]), fmaxf(sc[1][0], sc[1][1]));
            float m1 = fmaxf(fmaxf(sc[0][2], sc[0][3]), fmaxf(sc[1][2], sc[1][3]));
            m0 = fmaxf(m0, __shfl_xor_sync(0xffffffffu, m0, 1));
            m0 = fmaxf(m0, __shfl_xor_sync(0xffffffffu, m0, 2));
            m1 = fmaxf(m1, __shfl_xor_sync(0xffffffffu, m1, 1));
            m1 = fmaxf(m1, __shfl_xor_sync(0xffffffffu, m1, 2));
            float p[2][4];
            float sum0 = 0.f, sum1 = 0.f;
#pragma unroll
            for (int t = 0; t < 2; ++t) {
                p[t][0] = __expf(sc[t][0] - m0); p[t][1] = __expf(sc[t][1] - m0);
                p[t][2] = __expf(sc[t][2] - m1); p[t][3] = __expf(sc[t][3] - m1);
                sum0 += p[t][0] + p[t][1];
                sum1 += p[t][2] + p[t][3];
            }
            sum0 += __shfl_xor_sync(0xffffffffu, sum0, 1);
            sum0 += __shfl_xor_sync(0xffffffffu, sum0, 2);
            sum1 += __shfl_xor_sync(0xffffffffu, sum1, 1);
            sum1 += __shfl_xor_sync(0xffffffffu, sum1, 2);
            float i0 = 1.f / sum0, i1 = 1.f / sum1;
            aP[bi][0] = h2u(p[0][0] * i0, p[0][1] * i0);
            aP[bi][1] = h2u(p[0][2] * i1, p[0][3] * i1);
            aP[bi][2] = h2u(p[1][0] * i0, p[1][1] * i0);
            aP[bi][3] = h2u(p[1][2] * i1, p[1][3] * i1);
        }

        // V / ctx (fp16-accum) / proj (fp32) streamed per feature block
#pragma unroll
        for (int fb = 0; fb < 4; ++fb) {
            uint32_t vt[2][2][2];
            init8x2h(vt, bv + h * 64 + fb * 16, c2);
            wgemm16ch(ah16, wh + 1024, fb, lane, vt);

            uint32_t ca[2][4];
#pragma unroll
            for (int bi = 0; bi < 2; ++bi) {
                uint32_t bb[2];
                uint32_t cc0[2] = {0u, 0u};
                uint32_t cc1[2] = {0u, 0u};
                bb[0] = movm(vt[bi][0][0]);    // tile0: rows r block -> keys 0-7
                bb[1] = movm(vt[bi][0][1]);    //        rows r+8     -> keys 8-15
                mma16816h(cc0, aP[bi], bb);
                bb[0] = movm(vt[bi][1][0]);    // tile1
                bb[1] = movm(vt[bi][1][1]);
                mma16816h(cc1, aP[bi], bb);
                // ctx D-frags are directly proj A-frags
                ca[bi][0] = cc0[0];
                ca[bi][1] = cc0[1];
                ca[bi][2] = cc1[0];
                ca[bi][3] = cc1[1];
            }
            // pacc += ctx_fb @ Wp[k-step fb]
#pragma unroll
            for (int p = 0; p < 4; ++p) {
                uint4 q = __ldg(wh + 1536 + (fb * 4 + p) * 32 + lane);
                uint32_t bA[2] = {q.x, q.y}, bB[2] = {q.z, q.w};
#pragma unroll
                for (int bi = 0; bi < 2; ++bi) {
                    mma16816(pacc[bi][2 * p],     ca[bi], bA);
                    mma16816(pacc[bi][2 * p + 1], ca[bi], bB);
                }
            }
        }
    }

    // ---- x2 = x + pacc; stash; LN2 in registers -> A2 frags ----
    uint32_t A2[2][4][4];
#pragma unroll
    for (int bi = 0; bi < 2; ++bi) {
        float x2v[8][4];
#pragma unroll
        for (int j = 0; j < 8; ++j) {
            int col = c2 + 8 * j;
            float2 xa = *(const float2*)(xs + row0[bi] * LDF + col);
            float2 xb = *(const float2*)(xs + (row0[bi] + 8) * LDF + col);
            x2v[j][0] = xa.x + pacc[bi][j][0]; x2v[j][1] = xa.y + pacc[bi][j][1];
            x2v[j][2] = xb.x + pacc[bi][j][2]; x2v[j][3] = xb.y + pacc[bi][j][3];
            *(float2*)(xs + row0[bi] * LDF + col)       = make_float2(x2v[j][0], x2v[j][1]);
            *(float2*)(xs + (row0[bi] + 8) * LDF + col) = make_float2(x2v[j][2], x2v[j][3]);
        }
        float s0 = 0.f, q0 = 0.f, s1 = 0.f, q1 = 0.f;
#pragma unroll
        for (int j = 0; j < 8; ++j) {
            s0 += x2v[j][0] + x2v[j][1];
            q0 += x2v[j][0] * x2v[j][0] + x2v[j][1] * x2v[j][1];
            s1 += x2v[j][2] + x2v[j][3];
            q1 += x2v[j][2] * x2v[j][2] + x2v[j][3] * x2v[j][3];
        }
        s0 += __shfl_xor_sync(0xffffffffu, s0, 1); s0 += __shfl_xor_sync(0xffffffffu, s0, 2);
        q0 += __shfl_xor_sync(0xffffffffu, q0, 1); q0 += __shfl_xor_sync(0xffffffffu, q0, 2);
        s1 += __shfl_xor_sync(0xffffffffu, s1, 1); s1 += __shfl_xor_sync(0xffffffffu, s1, 2);
        q1 += __shfl_xor_sync(0xffffffffu, q1, 1); q1 += __shfl_xor_sync(0xffffffffu, q1, 2);
        float mean0 = s0 * (1.f / 64.f), inv0 = rsqrtf(q0 * (1.f / 64.f) - mean0 * mean0 + EPSV);
        float mean1 = s1 * (1.f / 64.f), inv1 = rsqrtf(q1 * (1.f / 64.f) - mean1 * mean1 + EPSV);
        float nv[8][4];
#pragma unroll
        for (int j = 0; j < 8; ++j) {
            int col = c2 + 8 * j;
            float2 gg = __ldg((const float2*)(g2 + col));
            float2 bb = __ldg((const float2*)(be2 + col));
            nv[j][0] = (x2v[j][0] - mean0) * inv0 * gg.x + bb.x;
            nv[j][1] = (x2v[j][1] - mean0) * inv0 * gg.y + bb.y;
            nv[j][2] = (x2v[j][2] - mean1) * inv1 * gg.x + bb.x;
            nv[j][3] = (x2v[j][3] - mean1) * inv1 * gg.y + bb.y;
        }
        c2a(nv, A2[bi]);
    }

    // ---- FFN: hidden in fp16-accum, FFN2 fp32, oacc in registers ----
    float oacc[2][8][4];
#pragma unroll
    for (int j = 0; j < 8; ++j) {
        float2 bv2 = __ldg((const float2*)(b2 + 8 * j + c2));
#pragma unroll
        for (int bi = 0; bi < 2; ++bi) {
            oacc[bi][j][0] = bv2.x; oacc[bi][j][1] = bv2.y;
            oacc[bi][j][2] = bv2.x; oacc[bi][j][3] = bv2.y;
        }
    }
#pragma unroll 1
    for (int cc = 0; cc < 4; ++cc) {
        const uint4* w1c = gWf + (16 + cc) * 512;
        const uint4* w2c = gWf + (20 + cc) * 512;
#pragma unroll
        for (int fb = 0; fb < 4; ++fb) {
            uint32_t ht[2][2][2];
            init8x2h(ht, b1 + cc * 64 + fb * 16, c2);
            wgemm16ch(A2, w1c, fb, lane, ht);
            uint32_t ha[2][4];
#pragma unroll
            for (int bi = 0; bi < 2; ++bi) {
                // relu on packed half2; D-frags are directly FFN2 A-frags
                ha[bi][0] = relu2(ht[bi][0][0]);
                ha[bi][1] = relu2(ht[bi][0][1]);
                ha[bi][2] = relu2(ht[bi][1][0]);
                ha[bi][3] = relu2(ht[bi][1][1]);
            }
#pragma unroll
            for (int p = 0; p < 4; ++p) {
                uint4 q = __ldg(w2c + (fb * 4 + p) * 32 + lane);
                uint32_t bA[2] = {q.x, q.y}, bB[2] = {q.z, q.w};
#pragma unroll
                for (int bi = 0; bi < 2; ++bi) {
                    mma16816(oacc[bi][2 * p],     ha[bi], bA);
                    mma16816(oacc[bi][2 * p + 1], ha[bi], bB);
                }
            }
        }
    }

    // ---- out = x2 + ffn ----
#pragma unroll
    for (int bi = 0; bi < 2; ++bi)
#pragma unroll
        for (int j = 0; j < 8; ++j) {
            int col = c2 + 8 * j;
            float2 xa = *(const float2*)(xs + row0[bi] * LDF + col);
            float2 xb = *(const float2*)(xs + (row0[bi] + 8) * LDF + col);
            *(float2*)(out + (size_t)(g0 + row0[bi]) * 64 + col) =
                make_float2(xa.x + oacc[bi][j][0], xa.y + oacc[bi][j][1]);
            *(float2*)(out + (size_t)(g0 + row0[bi] + 8) * 64 + col) =
                make_float2(xb.x + oacc[bi][j][2], xb.y + oacc[bi][j][3]);
        }
}

extern "C" void kernel_launch(void* const* d_in, const int* in_sizes, int n_in,
                              void* d_out, int out_size) {
    const float* x   = (const float*)d_in[0];
    const float* Wq  = (const float*)d_in[1];
    const float* bq  = (const float*)d_in[2];
    const float* Wk  = (const float*)d_in[3];
    const float* bk  = (const float*)d_in[4];
    const float* Wv  = (const float*)d_in[5];
    const float* bv  = (const float*)d_in[6];
    const float* Wp  = (const float*)d_in[7];
    const float* bp  = (const float*)d_in[8];
    const float* W1  = (const float*)d_in[9];
    const float* b1  = (const float*)d_in[10];
    const float* W2  = (const float*)d_in[11];
    const float* b2  = (const float*)d_in[12];
    const float* g1  = (const float*)d_in[13];
    const float* be1 = (const float*)d_in[14];
    const float* g2  = (const float*)d_in[15];
    const float* be2 = (const float*)d_in[16];
    float* out = (float*)d_out;

    pack_weights<<<24, 256>>>(Wq, Wk, Wv, Wp, W1, W2);

    const int smem_bytes = TOK * LDF * (int)sizeof(float);   // 34816
    cudaFuncSetAttribute(tblock_kernel, cudaFuncAttributeMaxDynamicSharedMemorySize, smem_bytes);

    dim3 grid(Bn / 8);   // 2048
    dim3 block(NTH);
    tblock_kernel<<<grid, block, smem_bytes>>>(x, bq, bk, bv, bp, b1, b2,
                                               g1, be1, g2, be2, out);
}